// round 9
// baseline (speedup 1.0000x reference)
#include <cuda_runtime.h>
#include <stdint.h>

// Binarized depthwise 3x3 conv, stride 1, SAME. x:(16,112,112,256) NHWC fp32,
// kernel:(3,3,256,1). out = sum of sign(x)*sign(k) over valid taps.
//
// bf16x2 math: pack 2 channels' fp32 high-halves into one reg (PRMT); per tap
// one LOP3 ((t & 0x80008000) ^ kp) yields bf16x2 of +-1.0 (or +-0.0 when kp
// is zeroed for a missing border row); accumulate with add.rn.bf16x2 (exact,
// |sum| <= 9). Streaming column recurrence per output row:
//   out[c-1] = A + q2(c); A = B + q1(c); B = q0(c)
//
// This round: 4 channels/thread -> LDG.128/STG.128 (half the memory ops of
// the float2 version, 2x bytes-in-flight per outstanding-load slot), keeping
// the row-pair structure (2 output rows from 4 input rows).

#define NN 16
#define HH 112
#define WW 112
#define CC 256
#define RS (WW * CC)            // row stride in elements

__device__ __forceinline__ uint32_t badd(uint32_t a, uint32_t b) {
    uint32_t r;
    asm("add.rn.bf16x2 %0, %1, %2;" : "=r"(r) : "r"(a), "r"(b));
    return r;
}

#define TAPP(t, kp) ((((t) & 0x80008000u)) ^ (kp))

// Load float4, pack to two bf16x2 sign-carriers (high halves of fp32 pairs).
__device__ __forceinline__ void pack4(const float* __restrict__ p,
                                      uint32_t& a, uint32_t& b) {
    const float4 v = *reinterpret_cast<const float4*>(p);
    a = __byte_perm(__float_as_uint(v.x), __float_as_uint(v.y), 0x7632);
    b = __byte_perm(__float_as_uint(v.z), __float_as_uint(v.w), 0x7632);
}

__device__ __forceinline__ void store4(float* __restrict__ p,
                                       uint32_t oa, uint32_t ob) {
    float4 o4;
    o4.x = __uint_as_float(oa << 16);
    o4.y = __uint_as_float(oa & 0xFFFF0000u);
    o4.z = __uint_as_float(ob << 16);
    o4.w = __uint_as_float(ob & 0xFFFF0000u);
    *reinterpret_cast<float4*>(p) = o4;
}

__global__ __launch_bounds__(128, 7)
void bconv_kernel(const float* __restrict__ x,
                  const float* __restrict__ k,
                  float* __restrict__ out) {
    const int hpair = blockIdx.x >> 1;          // 0..55 -> rows 2i, 2i+1
    const int spair = blockIdx.x & 1;           // strip pair
    const int n = blockIdx.y;
    const int t = threadIdx.x;
    const int quad = t & 63;                    // channel quad 0..63
    const int gs = spair * 2 + (t >> 6);        // global strip 0..3 (28 cols)
    const int c0 = quad * 4;

    const int h0 = hpair * 2;
    const bool hasT = (hpair != 0);
    const bool hasB = (hpair != 55);

    // Kernel signs as bf16x2 of +-1.0 per channel pair; [half] a=ch0/1, b=ch2/3.
    uint32_t kp[3][3][2];
#pragma unroll
    for (int kh = 0; kh < 3; ++kh)
#pragma unroll
        for (int kw = 0; kw < 3; ++kw) {
            const float4 kv = *reinterpret_cast<const float4*>(k + (kh * 3 + kw) * CC + c0);
            uint32_t s0 = (kv.x >= 0.0f) ? 0x3F80u : 0xBF80u;
            uint32_t s1 = (kv.y >= 0.0f) ? 0x3F80u : 0xBF80u;
            uint32_t s2 = (kv.z >= 0.0f) ? 0x3F80u : 0xBF80u;
            uint32_t s3 = (kv.w >= 0.0f) ? 0x3F80u : 0xBF80u;
            kp[kh][kw][0] = s0 | (s1 << 16);
            kp[kh][kw][1] = s2 | (s3 << 16);
        }
    // Border-zeroed outer taps (zeroed kp adds +-0.0 -> no-op).
    uint32_t kpA0[3][2], kpB2[3][2];
#pragma unroll
    for (int kw = 0; kw < 3; ++kw) {
#pragma unroll
        for (int hf = 0; hf < 2; ++hf) {
            kpA0[kw][hf] = hasT ? kp[0][kw][hf] : 0u;
            kpB2[kw][hf] = hasB ? kp[2][kw][hf] : 0u;
        }
    }

    // Input rows h0-1, h0, h0+1, h0+2; r2 = r1 + RS (constant offset).
    const float* r1 = x + (((size_t)n * HH + h0) * WW) * CC + c0;
    const float* r0 = hasT ? r1 - RS : r1;      // clamped; zeroed via kp
    const float* r3 = hasB ? r1 + 2 * RS : r1;  // clamped; zeroed via kp
    float*       oA = out + (((size_t)n * HH + h0) * WW) * CC + c0;

    const int ws = gs * (WW / 4);
    const int we = ws + (WW / 4);
    const int cbeg = (ws == 0) ? 0 : ws - 1;
    const int cend = (we == WW) ? WW - 1 : we;

    uint32_t AAa, AAb, BAa, BAb, ABa, ABb, BBa, BBb;

    // ---- peeled first column (no store) ----
    {
        const size_t cc = (size_t)cbeg * CC;
        uint32_t t0a, t0b, t1a, t1b, t2a, t2b, t3a, t3b;
        pack4(r0 + cc, t0a, t0b);
        pack4(r1 + cc, t1a, t1b);
        pack4(r1 + cc + RS, t2a, t2b);
        pack4(r3 + cc, t3a, t3b);
        BAa = badd(badd(TAPP(t0a, kpA0[0][0]), TAPP(t1a, kp[1][0][0])), TAPP(t2a, kp[2][0][0]));
        BAb = badd(badd(TAPP(t0b, kpA0[0][1]), TAPP(t1b, kp[1][0][1])), TAPP(t2b, kp[2][0][1]));
        AAa = badd(badd(TAPP(t0a, kpA0[1][0]), TAPP(t1a, kp[1][1][0])), TAPP(t2a, kp[2][1][0]));
        AAb = badd(badd(TAPP(t0b, kpA0[1][1]), TAPP(t1b, kp[1][1][1])), TAPP(t2b, kp[2][1][1]));
        BBa = badd(badd(TAPP(t1a, kp[0][0][0]), TAPP(t2a, kp[1][0][0])), TAPP(t3a, kpB2[0][0]));
        BBb = badd(badd(TAPP(t1b, kp[0][0][1]), TAPP(t2b, kp[1][0][1])), TAPP(t3b, kpB2[0][1]));
        ABa = badd(badd(TAPP(t1a, kp[0][1][0]), TAPP(t2a, kp[1][1][0])), TAPP(t3a, kpB2[1][0]));
        ABb = badd(badd(TAPP(t1b, kp[0][1][1]), TAPP(t2b, kp[1][1][1])), TAPP(t3b, kpB2[1][1]));
    }

    // ---- branchless main loop: load col c, store col c-1 (2 rows) ----
#pragma unroll 2
    for (int c = cbeg + 1; c <= cend; ++c) {
        const size_t cc = (size_t)c * CC;
        uint32_t t0a, t0b, t1a, t1b, t2a, t2b, t3a, t3b;
        pack4(r0 + cc, t0a, t0b);
        pack4(r1 + cc, t1a, t1b);
        pack4(r1 + cc + RS, t2a, t2b);
        pack4(r3 + cc, t3a, t3b);

        const size_t po = (size_t)(c - 1) * CC;

        // Row A (h0): t0,t1,t2 with kh 0,1,2 (top tap may be zeroed).
        {
            const uint32_t q0a = badd(badd(TAPP(t0a, kpA0[0][0]), TAPP(t1a, kp[1][0][0])), TAPP(t2a, kp[2][0][0]));
            const uint32_t q0b = badd(badd(TAPP(t0b, kpA0[0][1]), TAPP(t1b, kp[1][0][1])), TAPP(t2b, kp[2][0][1]));
            const uint32_t q1a = badd(badd(TAPP(t0a, kpA0[1][0]), TAPP(t1a, kp[1][1][0])), TAPP(t2a, kp[2][1][0]));
            const uint32_t q1b = badd(badd(TAPP(t0b, kpA0[1][1]), TAPP(t1b, kp[1][1][1])), TAPP(t2b, kp[2][1][1]));
            const uint32_t q2a = badd(badd(TAPP(t0a, kpA0[2][0]), TAPP(t1a, kp[1][2][0])), TAPP(t2a, kp[2][2][0]));
            const uint32_t q2b = badd(badd(TAPP(t0b, kpA0[2][1]), TAPP(t1b, kp[1][2][1])), TAPP(t2b, kp[2][2][1]));
            store4(oA + po, badd(AAa, q2a), badd(AAb, q2b));
            AAa = badd(BAa, q1a); BAa = q0a;
            AAb = badd(BAb, q1b); BAb = q0b;
        }
        // Row B (h0+1): t1,t2,t3 with kh 0,1,2 (bottom tap may be zeroed).
        {
            const uint32_t q0a = badd(badd(TAPP(t1a, kp[0][0][0]), TAPP(t2a, kp[1][0][0])), TAPP(t3a, kpB2[0][0]));
            const uint32_t q0b = badd(badd(TAPP(t1b, kp[0][0][1]), TAPP(t2b, kp[1][0][1])), TAPP(t3b, kpB2[0][1]));
            const uint32_t q1a = badd(badd(TAPP(t1a, kp[0][1][0]), TAPP(t2a, kp[1][1][0])), TAPP(t3a, kpB2[1][0]));
            const uint32_t q1b = badd(badd(TAPP(t1b, kp[0][1][1]), TAPP(t2b, kp[1][1][1])), TAPP(t3b, kpB2[1][1]));
            const uint32_t q2a = badd(badd(TAPP(t1a, kp[0][2][0]), TAPP(t2a, kp[1][2][0])), TAPP(t3a, kpB2[2][0]));
            const uint32_t q2b = badd(badd(TAPP(t1b, kp[0][2][1]), TAPP(t2b, kp[1][2][1])), TAPP(t3b, kpB2[2][1]));
            store4(oA + po + RS, badd(ABa, q2a), badd(ABb, q2b));
            ABa = badd(BBa, q1a); BBa = q0a;
            ABb = badd(BBb, q1b); BBb = q0b;
        }
    }

    if (we == WW) {  // right border: out[111] = q0(110) + q1(111) = A
        const size_t po = (size_t)(WW - 1) * CC;
        store4(oA + po,      AAa, AAb);
        store4(oA + po + RS, ABa, ABb);
    }
}

extern "C" void kernel_launch(void* const* d_in, const int* in_sizes, int n_in,
                              void* d_out, int out_size) {
    const float* x = (const float*)d_in[0];
    const float* k = (const float*)d_in[1];
    float* out = (float*)d_out;
    dim3 grid(112, NN);   // 112 = 56 row-pairs x 2 strip-pairs
    bconv_kernel<<<grid, 128>>>(x, k, out);
}